// round 1
// baseline (speedup 1.0000x reference)
#include <cuda_runtime.h>
#include <math.h>

#define BB 8
#define TT 8192
#define DD 1024
#define HH 16
#define HDIM 64
#define NSPLIT 16
#define CHUNK 512

// Scratch (static __device__ arrays — no allocation allowed)
__device__ float g_qkv[BB * 3 * DD];                 // [B, 3D]
__device__ float g_part[BB * HH * NSPLIT * 66];      // per-split: m, l, acc[64]
__device__ float g_yattn[BB * DD];                   // [B, H*HD]

// ---------------------------------------------------------------------------
// Init qkv accumulator with bias
__global__ void init_qkv_kernel(const float* __restrict__ b_attn) {
    int i = blockIdx.x * blockDim.x + threadIdx.x;
    if (i < BB * 3 * DD) g_qkv[i] = b_attn[i % (3 * DD)];
}

// ---------------------------------------------------------------------------
// Split-K GEMV-batch: out[b, j] += sum_i X[b, i] * W[i, j]   (Kdim = 1024)
// grid.x = N/256 column blocks, grid.y = 8 k-blocks of 128
__global__ void gemm_splitk_kernel(const float* __restrict__ X,
                                   const float* __restrict__ W,
                                   float* __restrict__ out, int N) {
    const int KB = 128;
    int j = blockIdx.x * 256 + threadIdx.x;
    int i0 = blockIdx.y * KB;

    __shared__ float xs[BB * KB];
    for (int r = threadIdx.x; r < BB * KB; r += 256) {
        int bb = r >> 7, ii = r & 127;
        xs[r] = X[bb * DD + i0 + ii];
    }
    __syncthreads();

    float acc[BB];
#pragma unroll
    for (int bb = 0; bb < BB; bb++) acc[bb] = 0.f;

    const float* Wp = W + (size_t)i0 * N + j;
#pragma unroll 4
    for (int ii = 0; ii < KB; ii++) {
        float w = Wp[(size_t)ii * N];
#pragma unroll
        for (int bb = 0; bb < BB; bb++)
            acc[bb] = fmaf(xs[bb * KB + ii], w, acc[bb]);
    }
#pragma unroll
    for (int bb = 0; bb < BB; bb++)
        atomicAdd(&out[bb * N + j], acc[bb]);
}

// ---------------------------------------------------------------------------
// Flash-decoding attention, split over time.
// grid = (NSPLIT, H, B), block = 256 (8 warps); warp w handles t = start+w, +8, ...
__global__ void attn_kernel(const float* __restrict__ past_k,
                            const float* __restrict__ past_v,
                            const int* __restrict__ idx) {
    const int split = blockIdx.x, h = blockIdx.y, b = blockIdx.z;
    const int tid = threadIdx.x, warp = tid >> 5, lane = tid & 31;
    const int id = idx[b];
    const int start = split * CHUNK;
    float* part = &g_part[(((size_t)b * HH + h) * NSPLIT + split) * 66];

    if (start > id) {  // nothing in this split
        if (tid == 0) { part[0] = -1e30f; part[1] = 0.f; }
        if (tid < 64) part[2 + tid] = 0.f;
        return;
    }
    const int end = min(start + CHUNK - 1, id);  // inclusive

    const float* qkv_b = g_qkv + b * 3 * DD;
    const float scale = 0.125f;  // 1/sqrt(64)
    float q0 = qkv_b[h * HDIM + 2 * lane] * scale;
    float q1 = qkv_b[h * HDIM + 2 * lane + 1] * scale;

    float m = -1e30f, l = 0.f, a0 = 0.f, a1 = 0.f;

    for (int t = start + warp; t <= end; t += 8) {
        const float* kp;
        const float* vp;
        if (t == id) {  // current-step k/v from qkv
            kp = qkv_b + DD + h * HDIM;
            vp = qkv_b + 2 * DD + h * HDIM;
        } else {
            size_t off = (((size_t)b * TT + t) * HH + h) * HDIM;
            kp = past_k + off;
            vp = past_v + off;
        }
        float2 kk = *(const float2*)(kp + 2 * lane);
        float s = q0 * kk.x + q1 * kk.y;
#pragma unroll
        for (int o = 16; o; o >>= 1) s += __shfl_xor_sync(0xffffffffu, s, o);

        float2 vv = *(const float2*)(vp + 2 * lane);
        float mn = fmaxf(m, s);
        float c = __expf(m - mn);
        float p = __expf(s - mn);
        l = l * c + p;
        a0 = a0 * c + p * vv.x;
        a1 = a1 * c + p * vv.y;
        m = mn;
    }

    // merge 8 warps
    __shared__ float sm[8], sl[8], sa[8][HDIM];
    if (lane == 0) { sm[warp] = m; sl[warp] = l; }
    sa[warp][2 * lane] = a0;
    sa[warp][2 * lane + 1] = a1;
    __syncthreads();

    if (tid < HDIM) {
        float M = -1e30f;
#pragma unroll
        for (int w = 0; w < 8; w++) M = fmaxf(M, sm[w]);
        float L = 0.f, A = 0.f;
#pragma unroll
        for (int w = 0; w < 8; w++) {
            float e = __expf(sm[w] - M);
            L += e * sl[w];
            A += e * sa[w][tid];
        }
        if (tid == 0) { part[0] = M; part[1] = L; }
        part[2 + tid] = A;
    }
}

// ---------------------------------------------------------------------------
// Combine split partials -> y_attn
__global__ void combine_kernel() {
    int bh = blockIdx.x;  // 0..127
    int b = bh / HH, h = bh % HH;
    int d = threadIdx.x;  // 0..63
    const float* base = g_part + (size_t)bh * NSPLIT * 66;

    float M = -1e30f;
#pragma unroll
    for (int s = 0; s < NSPLIT; s++) M = fmaxf(M, base[s * 66]);
    float L = 0.f, A = 0.f;
#pragma unroll
    for (int s = 0; s < NSPLIT; s++) {
        float e = __expf(base[s * 66] - M);
        L += e * base[s * 66 + 1];
        A += e * base[s * 66 + 2 + d];
    }
    g_yattn[b * DD + h * HDIM + d] = A / L;
}

// ---------------------------------------------------------------------------
// Write k_step / v_step outputs; init y region with b_proj for the proj GEMV
__global__ void copy_out_kernel(const float* __restrict__ b_proj,
                                float* __restrict__ out) {
    int i = blockIdx.x * blockDim.x + threadIdx.x;  // 0..24575
    if (i < BB * DD) {
        out[i] = b_proj[i % DD];
    } else if (i < 2 * BB * DD) {
        int lcl = i - BB * DD;
        int b = lcl / DD, j = lcl % DD;
        out[i] = g_qkv[b * 3 * DD + DD + j];       // k_step
    } else if (i < 3 * BB * DD) {
        int lcl = i - 2 * BB * DD;
        int b = lcl / DD, j = lcl % DD;
        out[i] = g_qkv[b * 3 * DD + 2 * DD + j];   // v_step
    }
}

// ---------------------------------------------------------------------------
extern "C" void kernel_launch(void* const* d_in, const int* in_sizes, int n_in,
                              void* d_out, int out_size) {
    const float* x      = (const float*)d_in[0];
    const float* past_k = (const float*)d_in[1];
    const float* past_v = (const float*)d_in[2];
    const int*   idx    = (const int*)d_in[3];
    const float* W_attn = (const float*)d_in[4];
    const float* b_attn = (const float*)d_in[5];
    const float* W_proj = (const float*)d_in[6];
    const float* b_proj = (const float*)d_in[7];
    float* out = (float*)d_out;

    float* qkv_ptr = nullptr;
    float* yattn_ptr = nullptr;
    cudaGetSymbolAddress((void**)&qkv_ptr, g_qkv);
    cudaGetSymbolAddress((void**)&yattn_ptr, g_yattn);

    // 1. qkv = bias
    init_qkv_kernel<<<24, 1024>>>(b_attn);
    // 2. qkv += x @ W_attn   (split-K, W read once)
    gemm_splitk_kernel<<<dim3(12, 8), 256>>>(x, W_attn, qkv_ptr, 3 * DD);
    // 3. flash-decode attention partials
    attn_kernel<<<dim3(NSPLIT, HH, BB), 256>>>(past_k, past_v, idx);
    // 4. combine splits
    combine_kernel<<<BB * HH, HDIM>>>();
    // 5. emit k_step/v_step, seed y with b_proj
    copy_out_kernel<<<24, 1024>>>(b_proj, out);
    // 6. y += y_attn @ W_proj
    gemm_splitk_kernel<<<dim3(4, 8), 256>>>(yattn_ptr, W_proj, out, DD);
}

// round 4
// speedup vs baseline: 2.7366x; 2.7366x over previous
#include <cuda_runtime.h>
#include <math.h>

#define BB 8
#define TT 8192
#define DD 1024
#define HH 16
#define HDIM 64
#define NSPLIT 32
#define CHUNK 256

#define NEG_INF (-__int_as_float(0x7f800000) * 1.0f)

// Scratch (static __device__ arrays — no allocation allowed)
__device__ float g_qkv[BB * 3 * DD];                 // [B, 3D]
__device__ float g_part[BB * HH * NSPLIT * 66];      // per-split: m, l, acc[64]
__device__ float g_yattn[BB * DD];                   // [B, H*HD]

// ---------------------------------------------------------------------------
// Init qkv accumulator with bias
__global__ void init_qkv_kernel(const float* __restrict__ b_attn) {
    int i = blockIdx.x * blockDim.x + threadIdx.x;
    if (i < BB * 3 * DD) g_qkv[i] = b_attn[i % (3 * DD)];
}

// ---------------------------------------------------------------------------
// Split-K GEMV-batch: out[b, j] += sum_i X[b, i] * W[i, j]   (Kdim = 1024)
// grid.x = N/256 column blocks, grid.y = 32 k-blocks of 32
__global__ void gemm_splitk_kernel(const float* __restrict__ X,
                                   const float* __restrict__ W,
                                   float* __restrict__ out, int N) {
    const int KB = 32;
    int j = blockIdx.x * 256 + threadIdx.x;
    int i0 = blockIdx.y * KB;

    __shared__ float xs[BB * KB];   // 256 floats
    {
        int bb = threadIdx.x >> 5, ii = threadIdx.x & 31;
        xs[threadIdx.x] = X[bb * DD + i0 + ii];
    }
    __syncthreads();

    float acc[BB];
#pragma unroll
    for (int bb = 0; bb < BB; bb++) acc[bb] = 0.f;

    const float* Wp = W + (size_t)i0 * N + j;
#pragma unroll
    for (int ii = 0; ii < KB; ii++) {
        float w = Wp[(size_t)ii * N];
#pragma unroll
        for (int bb = 0; bb < BB; bb++)
            acc[bb] = fmaf(xs[bb * KB + ii], w, acc[bb]);
    }
#pragma unroll
    for (int bb = 0; bb < BB; bb++)
        atomicAdd(&out[bb * N + j], acc[bb]);
}

// ---------------------------------------------------------------------------
// Flash-decoding attention, split over time.
// grid = (NSPLIT, H, B), block = 256 (8 warps).
// Each half-warp (16 lanes x float4) owns one timestep per iteration:
// warp w, half hw handles t = start + 2*w + hw + 16*i.
// Loop condition is WARP-UNIFORM (ballot); tail iterations are predicated
// with s = -inf so all shuffles run fully converged.
__global__ void attn_kernel(const float* __restrict__ past_k,
                            const float* __restrict__ past_v,
                            const int* __restrict__ idx) {
    const int split = blockIdx.x, h = blockIdx.y, b = blockIdx.z;
    const int id = idx[b];
    const int start = split * CHUNK;
    if (start > id) return;                       // inactive split: no writes
    const int end = min(start + CHUNK - 1, id);   // inclusive

    const int tid = threadIdx.x, warp = tid >> 5, lane = tid & 31;
    const int hw = lane >> 4, sub = lane & 15;

    const float* qkv_b = g_qkv + b * 3 * DD;
    float4 q = *(const float4*)(qkv_b + h * HDIM + 4 * sub);
    const float scale = 0.125f;  // 1/sqrt(64)
    q.x *= scale; q.y *= scale; q.z *= scale; q.w *= scale;

    float m = -1e30f, l = 0.f;
    float4 acc = make_float4(0.f, 0.f, 0.f, 0.f);

    int t = start + 2 * warp + hw;
    bool valid = (t <= end);
    float4 kk = make_float4(0.f, 0.f, 0.f, 0.f);
    float4 vv = make_float4(0.f, 0.f, 0.f, 0.f);
    if (valid) {
        size_t off = (((size_t)b * TT + t) * HH + h) * HDIM;
        const float* kp = (t == id) ? (qkv_b + DD + h * HDIM) : (past_k + off);
        const float* vp = (t == id) ? (qkv_b + 2 * DD + h * HDIM) : (past_v + off);
        kk = *(const float4*)(kp + 4 * sub);
        vv = *(const float4*)(vp + 4 * sub);
    }

    while (__ballot_sync(0xffffffffu, valid)) {
        int tn = t + 16;
        bool nvalid = (tn <= end);
        float4 kn = make_float4(0.f, 0.f, 0.f, 0.f);
        float4 vn = make_float4(0.f, 0.f, 0.f, 0.f);
        if (nvalid) {  // prefetch next K/V while computing current
            size_t off = (((size_t)b * TT + tn) * HH + h) * HDIM;
            const float* kp = (tn == id) ? (qkv_b + DD + h * HDIM) : (past_k + off);
            const float* vp = (tn == id) ? (qkv_b + 2 * DD + h * HDIM) : (past_v + off);
            kn = *(const float4*)(kp + 4 * sub);
            vn = *(const float4*)(vp + 4 * sub);
        }

        float s = q.x * kk.x + q.y * kk.y + q.z * kk.z + q.w * kk.w;
#pragma unroll
        for (int o = 8; o; o >>= 1) s += __shfl_xor_sync(0xffffffffu, s, o);
        if (!valid) s = NEG_INF;   // dead half-warp contributes p = 0

        float mn = fmaxf(m, s);    // m >= -1e30 always, so mn finite
        float c = __expf(m - mn);
        float p = __expf(s - mn);  // 0 for invalid lanes
        l = l * c + p;
        acc.x = acc.x * c + p * vv.x;
        acc.y = acc.y * c + p * vv.y;
        acc.z = acc.z * c + p * vv.z;
        acc.w = acc.w * c + p * vv.w;
        m = mn;

        kk = kn; vv = vn; t = tn; valid = nvalid;
    }

    // merge the two half-warps (dims match: both halves hold dims 4*sub..)
    {
        float mo = __shfl_xor_sync(0xffffffffu, m, 16);
        float lo = __shfl_xor_sync(0xffffffffu, l, 16);
        float4 ao;
        ao.x = __shfl_xor_sync(0xffffffffu, acc.x, 16);
        ao.y = __shfl_xor_sync(0xffffffffu, acc.y, 16);
        ao.z = __shfl_xor_sync(0xffffffffu, acc.z, 16);
        ao.w = __shfl_xor_sync(0xffffffffu, acc.w, 16);
        float M = fmaxf(m, mo);
        float e1 = __expf(m - M), e2 = __expf(mo - M);
        l = l * e1 + lo * e2;
        acc.x = acc.x * e1 + ao.x * e2;
        acc.y = acc.y * e1 + ao.y * e2;
        acc.z = acc.z * e1 + ao.z * e2;
        acc.w = acc.w * e1 + ao.w * e2;
        m = M;
    }

    // merge 8 warps via shared memory
    __shared__ float sm[8], sl[8];
    __shared__ float4 sa[8][16];
    if (lane == 0) { sm[warp] = m; sl[warp] = l; }
    if (hw == 0) sa[warp][sub] = acc;
    __syncthreads();

    if (tid < HDIM) {
        float M = -1e30f;
#pragma unroll
        for (int w = 0; w < 8; w++) M = fmaxf(M, sm[w]);
        float L = 0.f, A = 0.f;
#pragma unroll
        for (int w = 0; w < 8; w++) {
            float e = __expf(sm[w] - M);
            L += e * sl[w];
            A += e * ((const float*)&sa[w][0])[tid];
        }
        float* part = &g_part[(((size_t)b * HH + h) * NSPLIT + split) * 66];
        if (tid == 0) { part[0] = M; part[1] = L; }
        part[2 + tid] = A;
    }
}

// ---------------------------------------------------------------------------
// Combine split partials -> y_attn; also emits k_step/v_step and seeds out
// with b_proj (fused former copy_out). grid = 128 (bh), block = 256.
// Group g = tid/64 reduces splits s = g, g+4, ... then groups tree-merge.
__global__ void combine_kernel(const float* __restrict__ b_proj,
                               const int* __restrict__ idx,
                               float* __restrict__ out) {
    int bh = blockIdx.x;            // 0..127
    int b = bh >> 4, h = bh & 15;
    int g = threadIdx.x >> 6;       // 0..3
    int d = threadIdx.x & 63;
    int nact = idx[b] / CHUNK + 1;  // active splits
    const float* base = g_part + (size_t)bh * NSPLIT * 66;

    float M = -1e30f;
    for (int s = g; s < nact; s += 4) M = fmaxf(M, base[s * 66]);
    float L = 0.f, A = 0.f;
    for (int s = g; s < nact; s += 4) {
        float e = __expf(base[s * 66] - M);
        L += e * base[s * 66 + 1];
        A += e * base[s * 66 + 2 + d];
    }

    __shared__ float shm[4], shl[4], sha[4][HDIM];
    if (d == 0) { shm[g] = M; shl[g] = L; }
    sha[g][d] = A;
    __syncthreads();

    if (g == 0) {
        float MM = fmaxf(fmaxf(shm[0], shm[1]), fmaxf(shm[2], shm[3]));
        float LL = 0.f, AA = 0.f;
#pragma unroll
        for (int gg = 0; gg < 4; gg++) {
            float e = __expf(shm[gg] - MM);
            LL += e * shl[gg];
            AA += e * sha[gg][d];
        }
        g_yattn[b * DD + h * HDIM + d] = AA / LL;
    }

    // fused output writes (independent of the reduction above)
    int j = h * HDIM + d;
    if (g == 1) out[b * DD + j] = b_proj[j];                              // y seed
    else if (g == 2) out[BB * DD + b * DD + j] = g_qkv[b * 3 * DD + DD + j];      // k_step
    else if (g == 3) out[2 * BB * DD + b * DD + j] = g_qkv[b * 3 * DD + 2 * DD + j]; // v_step
}

// ---------------------------------------------------------------------------
extern "C" void kernel_launch(void* const* d_in, const int* in_sizes, int n_in,
                              void* d_out, int out_size) {
    const float* x      = (const float*)d_in[0];
    const float* past_k = (const float*)d_in[1];
    const float* past_v = (const float*)d_in[2];
    const int*   idx    = (const int*)d_in[3];
    const float* W_attn = (const float*)d_in[4];
    const float* b_attn = (const float*)d_in[5];
    const float* W_proj = (const float*)d_in[6];
    const float* b_proj = (const float*)d_in[7];
    float* out = (float*)d_out;

    float* qkv_ptr = nullptr;
    float* yattn_ptr = nullptr;
    cudaGetSymbolAddress((void**)&qkv_ptr, g_qkv);
    cudaGetSymbolAddress((void**)&yattn_ptr, g_yattn);

    // 1. qkv = bias
    init_qkv_kernel<<<24, 1024>>>(b_attn);
    // 2. qkv += x @ W_attn   (split-K 32-wide, W read once)
    gemm_splitk_kernel<<<dim3(12, 32), 256>>>(x, W_attn, qkv_ptr, 3 * DD);
    // 3. flash-decode attention partials (32 time-splits)
    attn_kernel<<<dim3(NSPLIT, HH, BB), 256>>>(past_k, past_v, idx);
    // 4. combine splits + emit k_step/v_step + seed y with b_proj
    combine_kernel<<<BB * HH, 256>>>(b_proj, idx, out);
    // 5. y += y_attn @ W_proj
    gemm_splitk_kernel<<<dim3(4, 32), 256>>>(yattn_ptr, W_proj, out, DD);
}

// round 6
// speedup vs baseline: 2.8488x; 1.0410x over previous
#include <cuda_runtime.h>
#include <math.h>

#define BB 8
#define TT 8192
#define DD 1024
#define HH 16
#define HDIM 64
#define NSPLIT 32
#define CHUNK 256

#define NEG_INF (-__int_as_float(0x7f800000) * 1.0f)

// Scratch (static __device__ arrays — no allocation allowed)
__device__ float g_qkv[BB * 3 * DD];                 // [B, 3D]
__device__ float g_part[BB * HH * NSPLIT * 66];      // per-split: m, l, acc[64]
__device__ float g_yattn[BB * DD];                   // [B, H*HD]
__device__ int   g_cnt[BB * HH];                     // arrival counters (self-resetting)

// ---------------------------------------------------------------------------
// Init qkv accumulator with bias
__global__ void init_qkv_kernel(const float* __restrict__ b_attn) {
    int i = blockIdx.x * blockDim.x + threadIdx.x;
    if (i < BB * 3 * DD) g_qkv[i] = b_attn[i % (3 * DD)];
}

// ---------------------------------------------------------------------------
// Split-K GEMV-batch: out[b, j] += sum_i X[b, i] * W[i, j]   (Kdim = 1024)
// grid.x = N/256 column blocks, grid.y = 32 k-blocks of 32
__global__ void gemm_splitk_kernel(const float* __restrict__ X,
                                   const float* __restrict__ W,
                                   float* __restrict__ out, int N) {
    const int KB = 32;
    int j = blockIdx.x * 256 + threadIdx.x;
    int i0 = blockIdx.y * KB;

    __shared__ float xs[BB * KB];   // 256 floats
    {
        int bb = threadIdx.x >> 5, ii = threadIdx.x & 31;
        xs[threadIdx.x] = X[bb * DD + i0 + ii];
    }
    __syncthreads();

    float acc[BB];
#pragma unroll
    for (int bb = 0; bb < BB; bb++) acc[bb] = 0.f;

    const float* Wp = W + (size_t)i0 * N + j;
#pragma unroll
    for (int ii = 0; ii < KB; ii++) {
        float w = Wp[(size_t)ii * N];
#pragma unroll
        for (int bb = 0; bb < BB; bb++)
            acc[bb] = fmaf(xs[bb * KB + ii], w, acc[bb]);
    }
#pragma unroll
    for (int bb = 0; bb < BB; bb++)
        atomicAdd(&out[bb * N + j], acc[bb]);
}

// ---------------------------------------------------------------------------
// Flash-decoding attention, split over time, with FUSED split-combine:
// the last block to finish for a given (b,h) merges all split partials,
// writes y_attn, and emits k_step/v_step + b_proj seed to out.
// grid = (NSPLIT, H, B), block = 256 (8 warps).
__global__ void attn_kernel(const float* __restrict__ past_k,
                            const float* __restrict__ past_v,
                            const int* __restrict__ idx,
                            const float* __restrict__ b_proj,
                            float* __restrict__ out) {
    const int split = blockIdx.x, h = blockIdx.y, b = blockIdx.z;
    const int id = idx[b];
    const int start = split * CHUNK;
    if (start > id) return;                       // inactive split: no writes
    const int end = min(start + CHUNK - 1, id);   // inclusive
    const int nact = id / CHUNK + 1;              // number of active splits

    const int tid = threadIdx.x, warp = tid >> 5, lane = tid & 31;
    const int hw = lane >> 4, sub = lane & 15;

    const float* qkv_b = g_qkv + b * 3 * DD;
    float4 q = *(const float4*)(qkv_b + h * HDIM + 4 * sub);
    const float scale = 0.125f;  // 1/sqrt(64)
    q.x *= scale; q.y *= scale; q.z *= scale; q.w *= scale;

    float m = -1e30f, l = 0.f;
    float4 acc = make_float4(0.f, 0.f, 0.f, 0.f);

    int t = start + 2 * warp + hw;
    bool valid = (t <= end);
    float4 kk = make_float4(0.f, 0.f, 0.f, 0.f);
    float4 vv = make_float4(0.f, 0.f, 0.f, 0.f);
    if (valid) {
        size_t off = (((size_t)b * TT + t) * HH + h) * HDIM;
        const float* kp = (t == id) ? (qkv_b + DD + h * HDIM) : (past_k + off);
        const float* vp = (t == id) ? (qkv_b + 2 * DD + h * HDIM) : (past_v + off);
        kk = *(const float4*)(kp + 4 * sub);
        vv = *(const float4*)(vp + 4 * sub);
    }

    while (__ballot_sync(0xffffffffu, valid)) {
        int tn = t + 16;
        bool nvalid = (tn <= end);
        float4 kn = make_float4(0.f, 0.f, 0.f, 0.f);
        float4 vn = make_float4(0.f, 0.f, 0.f, 0.f);
        if (nvalid) {  // prefetch next K/V while computing current
            size_t off = (((size_t)b * TT + tn) * HH + h) * HDIM;
            const float* kp = (tn == id) ? (qkv_b + DD + h * HDIM) : (past_k + off);
            const float* vp = (tn == id) ? (qkv_b + 2 * DD + h * HDIM) : (past_v + off);
            kn = *(const float4*)(kp + 4 * sub);
            vn = *(const float4*)(vp + 4 * sub);
        }

        float s = q.x * kk.x + q.y * kk.y + q.z * kk.z + q.w * kk.w;
#pragma unroll
        for (int o = 8; o; o >>= 1) s += __shfl_xor_sync(0xffffffffu, s, o);
        if (!valid) s = NEG_INF;   // dead half-warp contributes p = 0

        float mn = fmaxf(m, s);    // m >= -1e30 always, so mn finite
        float c = __expf(m - mn);
        float p = __expf(s - mn);  // 0 for invalid lanes
        l = l * c + p;
        acc.x = acc.x * c + p * vv.x;
        acc.y = acc.y * c + p * vv.y;
        acc.z = acc.z * c + p * vv.z;
        acc.w = acc.w * c + p * vv.w;
        m = mn;

        kk = kn; vv = vn; t = tn; valid = nvalid;
    }

    // merge the two half-warps (dims match: both halves hold dims 4*sub..)
    {
        float mo = __shfl_xor_sync(0xffffffffu, m, 16);
        float lo = __shfl_xor_sync(0xffffffffu, l, 16);
        float4 ao;
        ao.x = __shfl_xor_sync(0xffffffffu, acc.x, 16);
        ao.y = __shfl_xor_sync(0xffffffffu, acc.y, 16);
        ao.z = __shfl_xor_sync(0xffffffffu, acc.z, 16);
        ao.w = __shfl_xor_sync(0xffffffffu, acc.w, 16);
        float M = fmaxf(m, mo);
        float e1 = __expf(m - M), e2 = __expf(mo - M);
        l = l * e1 + lo * e2;
        acc.x = acc.x * e1 + ao.x * e2;
        acc.y = acc.y * e1 + ao.y * e2;
        acc.z = acc.z * e1 + ao.z * e2;
        acc.w = acc.w * e1 + ao.w * e2;
        m = M;
    }

    // merge 8 warps via shared memory
    __shared__ float sm[8], sl[8];
    __shared__ float4 sa[8][16];
    if (lane == 0) { sm[warp] = m; sl[warp] = l; }
    if (hw == 0) sa[warp][sub] = acc;
    __syncthreads();

    float* part_base0 = &g_part[((size_t)b * HH + h) * NSPLIT * 66];
    if (tid < HDIM) {
        float M = -1e30f;
#pragma unroll
        for (int w = 0; w < 8; w++) M = fmaxf(M, sm[w]);
        float L = 0.f, A = 0.f;
#pragma unroll
        for (int w = 0; w < 8; w++) {
            float e = __expf(sm[w] - M);
            L += e * sl[w];
            A += e * ((const float*)&sa[w][0])[tid];
        }
        float* part = part_base0 + (size_t)split * 66;
        if (tid == 0) { part[0] = M; part[1] = L; }
        part[2 + tid] = A;
    }
    __syncthreads();

    // ---- last-block-done: the final arriving block combines all splits ----
    __shared__ int is_last;
    if (tid == 0) {
        __threadfence();                         // publish partials
        int old = atomicAdd(&g_cnt[b * HH + h], 1);
        is_last = (old == nact - 1);
        if (is_last) g_cnt[b * HH + h] = 0;      // self-reset for next replay
    }
    __syncthreads();
    if (!is_last) return;

    // stage all active partials into smem with parallel (high-MLP) loads
    __shared__ float sp[NSPLIT * 66];
    int tot = nact * 66;
    for (int i = tid; i < tot; i += 256) sp[i] = part_base0[i];
    __syncthreads();

    // 4 groups x 64 dims reduction over splits
    int g = tid >> 6;       // 0..3
    int d = tid & 63;

    float M = -1e30f;
    for (int s = g; s < nact; s += 4) M = fmaxf(M, sp[s * 66]);
    float L = 0.f, A = 0.f;
    for (int s = g; s < nact; s += 4) {
        float e = __expf(sp[s * 66] - M);
        L += e * sp[s * 66 + 1];
        A += e * sp[s * 66 + 2 + d];
    }

    __shared__ float shm[4], shl[4], sha[4][HDIM];
    if (d == 0) { shm[g] = M; shl[g] = L; }
    sha[g][d] = A;
    __syncthreads();

    int j = h * HDIM + d;
    if (g == 0) {
        float MM = fmaxf(fmaxf(shm[0], shm[1]), fmaxf(shm[2], shm[3]));
        float LL = 0.f, AA = 0.f;
#pragma unroll
        for (int gg = 0; gg < 4; gg++) {
            float e = __expf(shm[gg] - MM);
            LL += e * shl[gg];
            AA += e * sha[gg][d];
        }
        g_yattn[b * DD + j] = AA / LL;
    } else if (g == 1) {
        out[b * DD + j] = b_proj[j];                                   // y seed
    } else if (g == 2) {
        out[BB * DD + b * DD + j] = qkv_b[DD + j];                     // k_step
    } else {
        out[2 * BB * DD + b * DD + j] = qkv_b[2 * DD + j];             // v_step
    }
}

// ---------------------------------------------------------------------------
extern "C" void kernel_launch(void* const* d_in, const int* in_sizes, int n_in,
                              void* d_out, int out_size) {
    const float* x      = (const float*)d_in[0];
    const float* past_k = (const float*)d_in[1];
    const float* past_v = (const float*)d_in[2];
    const int*   idx    = (const int*)d_in[3];
    const float* W_attn = (const float*)d_in[4];
    const float* b_attn = (const float*)d_in[5];
    const float* W_proj = (const float*)d_in[6];
    const float* b_proj = (const float*)d_in[7];
    float* out = (float*)d_out;

    float* qkv_ptr = nullptr;
    float* yattn_ptr = nullptr;
    cudaGetSymbolAddress((void**)&qkv_ptr, g_qkv);
    cudaGetSymbolAddress((void**)&yattn_ptr, g_yattn);

    // 1. qkv = bias
    init_qkv_kernel<<<24, 1024>>>(b_attn);
    // 2. qkv += x @ W_attn   (split-K 32-wide, W read once)
    gemm_splitk_kernel<<<dim3(12, 32), 256>>>(x, W_attn, qkv_ptr, 3 * DD);
    // 3. flash-decode attention partials + fused combine/output-emit
    attn_kernel<<<dim3(NSPLIT, HH, BB), 256>>>(past_k, past_v, idx, b_proj, out);
    // 4. y += y_attn @ W_proj
    gemm_splitk_kernel<<<dim3(4, 32), 256>>>(yattn_ptr, W_proj, out, DD);
}

// round 9
// speedup vs baseline: 2.9200x; 1.0250x over previous
#include <cuda_runtime.h>
#include <math.h>

#define BB 8
#define TT 8192
#define DD 1024
#define HH 16
#define HDIM 64
#define NSPLIT 32
#define CHUNK 256

#define NEG_INF (-__int_as_float(0x7f800000) * 1.0f)

// Scratch (static __device__ arrays — no allocation allowed)
__device__ float g_qkv[BB * 3 * DD];                 // [B, 3D]
__device__ float g_part[BB * HH * NSPLIT * 66];      // per-split: m, l, acc[64]
__device__ float g_yattn[BB * DD];                   // [B, H*HD]
__device__ int   g_cnt[BB * HH];                     // arrival counters (self-resetting)

// ---------------------------------------------------------------------------
// Init: qkv = bias (broadcast), and seed out's y region with b_proj
__global__ void init_qkv_kernel(const float* __restrict__ b_attn,
                                const float* __restrict__ b_proj,
                                float* __restrict__ out) {
    int i = blockIdx.x * blockDim.x + threadIdx.x;
    if (i < BB * 3 * DD) g_qkv[i] = b_attn[i % (3 * DD)];
    if (i < BB * DD) out[i] = b_proj[i % DD];
}

// ---------------------------------------------------------------------------
// Split-K GEMV-batch: out[b, j] += sum_i X[b, i] * W[i, j]   (Kdim = 1024)
// grid.x = N/256 column blocks, grid.y = 32 k-blocks of 32.
// W loads are explicitly batched into w[32] BEFORE any FMA consumes them,
// forcing MLP=32 (without this, ptxas register-budgets to MLP~1-2 and the
// kernel serializes on DRAM latency: measured 489 GB/s in R6).
__global__ void __launch_bounds__(256) gemm_splitk_kernel(
        const float* __restrict__ X,
        const float* __restrict__ W,
        float* __restrict__ out, int N) {
    const int KB = 32;
    int j = blockIdx.x * 256 + threadIdx.x;
    int i0 = blockIdx.y * KB;

    __shared__ float xs[BB * KB];   // 256 floats
    {
        int bb = threadIdx.x >> 5, ii = threadIdx.x & 31;
        xs[threadIdx.x] = X[bb * DD + i0 + ii];
    }

    // batch-issue all 32 weight loads (independent lines, full MLP)
    float w[KB];
    const float* Wp = W + (size_t)i0 * N + j;
#pragma unroll
    for (int ii = 0; ii < KB; ii++) w[ii] = Wp[(size_t)ii * N];

    __syncthreads();

    float acc[BB];
#pragma unroll
    for (int bb = 0; bb < BB; bb++) acc[bb] = 0.f;

#pragma unroll
    for (int ii = 0; ii < KB; ii++) {
#pragma unroll
        for (int bb = 0; bb < BB; bb++)
            acc[bb] = fmaf(xs[bb * KB + ii], w[ii], acc[bb]);
    }
#pragma unroll
    for (int bb = 0; bb < BB; bb++)
        atomicAdd(&out[bb * N + j], acc[bb]);
}

// ---------------------------------------------------------------------------
// Flash-decoding attention, split over time, with FUSED split-combine:
// the last block to finish for a given (b,h) merges all split partials,
// writes y_attn, and emits k_step/v_step to out.
// grid = (NSPLIT, H, B), block = 256 (8 warps).
__global__ void attn_kernel(const float* __restrict__ past_k,
                            const float* __restrict__ past_v,
                            const int* __restrict__ idx,
                            float* __restrict__ out) {
    const int split = blockIdx.x, h = blockIdx.y, b = blockIdx.z;
    const int id = idx[b];
    const int start = split * CHUNK;
    if (start > id) return;                       // inactive split: no writes
    const int end = min(start + CHUNK - 1, id);   // inclusive
    const int nact = id / CHUNK + 1;              // number of active splits

    const int tid = threadIdx.x, warp = tid >> 5, lane = tid & 31;
    const int hw = lane >> 4, sub = lane & 15;

    const float* qkv_b = g_qkv + b * 3 * DD;
    float4 q = *(const float4*)(qkv_b + h * HDIM + 4 * sub);
    const float scale = 0.125f;  // 1/sqrt(64)
    q.x *= scale; q.y *= scale; q.z *= scale; q.w *= scale;

    float m = -1e30f, l = 0.f;
    float4 acc = make_float4(0.f, 0.f, 0.f, 0.f);

    int t = start + 2 * warp + hw;
    bool valid = (t <= end);
    float4 kk = make_float4(0.f, 0.f, 0.f, 0.f);
    float4 vv = make_float4(0.f, 0.f, 0.f, 0.f);
    if (valid) {
        size_t off = (((size_t)b * TT + t) * HH + h) * HDIM;
        const float* kp = (t == id) ? (qkv_b + DD + h * HDIM) : (past_k + off);
        const float* vp = (t == id) ? (qkv_b + 2 * DD + h * HDIM) : (past_v + off);
        kk = *(const float4*)(kp + 4 * sub);
        vv = *(const float4*)(vp + 4 * sub);
    }

    while (__ballot_sync(0xffffffffu, valid)) {
        int tn = t + 16;
        bool nvalid = (tn <= end);
        float4 kn = make_float4(0.f, 0.f, 0.f, 0.f);
        float4 vn = make_float4(0.f, 0.f, 0.f, 0.f);
        if (nvalid) {  // prefetch next K/V while computing current
            size_t off = (((size_t)b * TT + tn) * HH + h) * HDIM;
            const float* kp = (tn == id) ? (qkv_b + DD + h * HDIM) : (past_k + off);
            const float* vp = (tn == id) ? (qkv_b + 2 * DD + h * HDIM) : (past_v + off);
            kn = *(const float4*)(kp + 4 * sub);
            vn = *(const float4*)(vp + 4 * sub);
        }

        float s = q.x * kk.x + q.y * kk.y + q.z * kk.z + q.w * kk.w;
#pragma unroll
        for (int o = 8; o; o >>= 1) s += __shfl_xor_sync(0xffffffffu, s, o);
        if (!valid) s = NEG_INF;   // dead half-warp contributes p = 0

        float mn = fmaxf(m, s);    // m >= -1e30 always, so mn finite
        float c = __expf(m - mn);
        float p = __expf(s - mn);  // 0 for invalid lanes
        l = l * c + p;
        acc.x = acc.x * c + p * vv.x;
        acc.y = acc.y * c + p * vv.y;
        acc.z = acc.z * c + p * vv.z;
        acc.w = acc.w * c + p * vv.w;
        m = mn;

        kk = kn; vv = vn; t = tn; valid = nvalid;
    }

    // merge the two half-warps (dims match: both halves hold dims 4*sub..)
    {
        float mo = __shfl_xor_sync(0xffffffffu, m, 16);
        float lo = __shfl_xor_sync(0xffffffffu, l, 16);
        float4 ao;
        ao.x = __shfl_xor_sync(0xffffffffu, acc.x, 16);
        ao.y = __shfl_xor_sync(0xffffffffu, acc.y, 16);
        ao.z = __shfl_xor_sync(0xffffffffu, acc.z, 16);
        ao.w = __shfl_xor_sync(0xffffffffu, acc.w, 16);
        float M = fmaxf(m, mo);
        float e1 = __expf(m - M), e2 = __expf(mo - M);
        l = l * e1 + lo * e2;
        acc.x = acc.x * e1 + ao.x * e2;
        acc.y = acc.y * e1 + ao.y * e2;
        acc.z = acc.z * e1 + ao.z * e2;
        acc.w = acc.w * e1 + ao.w * e2;
        m = M;
    }

    // merge 8 warps via shared memory
    __shared__ float sm[8], sl[8];
    __shared__ float4 sa[8][16];
    if (lane == 0) { sm[warp] = m; sl[warp] = l; }
    if (hw == 0) sa[warp][sub] = acc;
    __syncthreads();

    float* part_base0 = &g_part[((size_t)b * HH + h) * NSPLIT * 66];
    if (tid < HDIM) {
        float M = -1e30f;
#pragma unroll
        for (int w = 0; w < 8; w++) M = fmaxf(M, sm[w]);
        float L = 0.f, A = 0.f;
#pragma unroll
        for (int w = 0; w < 8; w++) {
            float e = __expf(sm[w] - M);
            L += e * sl[w];
            A += e * ((const float*)&sa[w][0])[tid];
        }
        float* part = part_base0 + (size_t)split * 66;
        if (tid == 0) { part[0] = M; part[1] = L; }
        part[2 + tid] = A;
    }
    __syncthreads();

    // ---- last-block-done: the final arriving block combines all splits ----
    __shared__ int is_last;
    if (tid == 0) {
        __threadfence();                         // publish partials
        int old = atomicAdd(&g_cnt[b * HH + h], 1);
        is_last = (old == nact - 1);
        if (is_last) g_cnt[b * HH + h] = 0;      // self-reset for next replay
    }
    __syncthreads();
    if (!is_last) return;

    // stage all active partials into smem with parallel (high-MLP) loads
    __shared__ float sp[NSPLIT * 66];
    int tot = nact * 66;
    for (int i = tid; i < tot; i += 256) sp[i] = part_base0[i];
    __syncthreads();

    // 4 groups x 64 dims reduction over splits
    int g = tid >> 6;       // 0..3
    int d = tid & 63;

    float M = -1e30f;
    for (int s = g; s < nact; s += 4) M = fmaxf(M, sp[s * 66]);
    float L = 0.f, A = 0.f;
    for (int s = g; s < nact; s += 4) {
        float e = __expf(sp[s * 66] - M);
        L += e * sp[s * 66 + 1];
        A += e * sp[s * 66 + 2 + d];
    }

    __shared__ float shm[4], shl[4], sha[4][HDIM];
    if (d == 0) { shm[g] = M; shl[g] = L; }
    sha[g][d] = A;
    __syncthreads();

    int j = h * HDIM + d;
    if (g == 0) {
        float MM = fmaxf(fmaxf(shm[0], shm[1]), fmaxf(shm[2], shm[3]));
        float LL = 0.f, AA = 0.f;
#pragma unroll
        for (int gg = 0; gg < 4; gg++) {
            float e = __expf(shm[gg] - MM);
            LL += e * shl[gg];
            AA += e * sha[gg][d];
        }
        g_yattn[b * DD + j] = AA / LL;
    } else if (g == 2) {
        out[BB * DD + b * DD + j] = qkv_b[DD + j];                     // k_step
    } else if (g == 3) {
        out[2 * BB * DD + b * DD + j] = qkv_b[2 * DD + j];             // v_step
    }
}

// ---------------------------------------------------------------------------
extern "C" void kernel_launch(void* const* d_in, const int* in_sizes, int n_in,
                              void* d_out, int out_size) {
    const float* x      = (const float*)d_in[0];
    const float* past_k = (const float*)d_in[1];
    const float* past_v = (const float*)d_in[2];
    const int*   idx    = (const int*)d_in[3];
    const float* W_attn = (const float*)d_in[4];
    const float* b_attn = (const float*)d_in[5];
    const float* W_proj = (const float*)d_in[6];
    const float* b_proj = (const float*)d_in[7];
    float* out = (float*)d_out;

    float* qkv_ptr = nullptr;
    float* yattn_ptr = nullptr;
    cudaGetSymbolAddress((void**)&qkv_ptr, g_qkv);
    cudaGetSymbolAddress((void**)&yattn_ptr, g_yattn);

    // 1. qkv = bias; out y-region = b_proj
    init_qkv_kernel<<<24, 1024>>>(b_attn, b_proj, out);
    // 2. qkv += x @ W_attn   (split-K, explicit MLP-32 load batch)
    gemm_splitk_kernel<<<dim3(12, 32), 256>>>(x, W_attn, qkv_ptr, 3 * DD);
    // 3. flash-decode attention partials + fused combine/output-emit
    attn_kernel<<<dim3(NSPLIT, HH, BB), 256>>>(past_k, past_v, idx, out);
    // 4. y += y_attn @ W_proj
    gemm_splitk_kernel<<<dim3(4, 32), 256>>>(yattn_ptr, W_proj, out, DD);
}

// round 10
// speedup vs baseline: 3.0165x; 1.0331x over previous
#include <cuda_runtime.h>
#include <math.h>

#define BB 8
#define TT 8192
#define DD 1024
#define HH 16
#define HDIM 64
#define NSPLIT 32
#define CHUNK 256

#define NEG_INF (-__int_as_float(0x7f800000) * 1.0f)

// Scratch (static __device__ arrays — no allocation allowed)
__device__ float g_qkv[BB * 3 * DD];                 // [B, 3D]
__device__ float g_part[BB * HH * NSPLIT * 66];      // per-split: m, l, acc[64]
__device__ float g_yattn[BB * DD];                   // [B, H*HD]
__device__ int   g_cnt[BB * HH];                     // arrival counters (self-resetting)

// ---------------------------------------------------------------------------
// Init: qkv = bias (broadcast), and seed out's y region with b_proj
__global__ void init_qkv_kernel(const float* __restrict__ b_attn,
                                const float* __restrict__ b_proj,
                                float* __restrict__ out) {
    int i = blockIdx.x * blockDim.x + threadIdx.x;
    if (i < BB * 3 * DD) g_qkv[i] = b_attn[i % (3 * DD)];
    if (i < BB * DD) out[i] = b_proj[i % DD];
}

// ---------------------------------------------------------------------------
// Split-K GEMV-batch: out[b, j] += sum_i X[b, i] * W[i, j]   (Kdim = 1024)
// grid.x = N/256 column blocks, grid.y = 32 k-blocks of 32.
// The W tile is staged through shared memory with cp.async (LDGSTS):
// fire-and-forget copies have no destination register, so ptxas CANNOT
// serialize them — all 32 lines/warp are in flight at once. (R6/R9 showed
// register-based batching collapses to MLP~1: 511 GB/s, 8.35us.)
__global__ void __launch_bounds__(256) gemm_splitk_kernel(
        const float* __restrict__ X,
        const float* __restrict__ W,
        float* __restrict__ out, int N) {
    const int KB = 32;
    const int tid = threadIdx.x;
    int j = blockIdx.x * 256 + tid;
    int i0 = blockIdx.y * KB;

    __shared__ float xs[BB * KB];      // 1 KB
    __shared__ float ws[KB][256];      // 32 KB

    // async-stage the 32x256 W tile (coalesced: 256 threads span one row)
    const float* Wp = W + (size_t)i0 * N + j;
    unsigned ws_base = (unsigned)__cvta_generic_to_shared(&ws[0][tid]);
#pragma unroll
    for (int ii = 0; ii < KB; ii++) {
        asm volatile("cp.async.ca.shared.global [%0], [%1], 4;\n"
                     :: "r"(ws_base + ii * 256 * 4),
                        "l"(Wp + (size_t)ii * N));
    }
    asm volatile("cp.async.commit_group;\n" ::: "memory");

    // x tile via regular load (tiny; overlaps the async group)
    {
        int bb = tid >> 5, ii = tid & 31;
        xs[tid] = X[bb * DD + i0 + ii];
    }

    asm volatile("cp.async.wait_group 0;\n" ::: "memory");
    __syncthreads();

    float acc[BB];
#pragma unroll
    for (int bb = 0; bb < BB; bb++) acc[bb] = 0.f;

#pragma unroll
    for (int ii = 0; ii < KB; ii++) {
        float w = ws[ii][tid];
#pragma unroll
        for (int bb = 0; bb < BB; bb++)
            acc[bb] = fmaf(xs[bb * KB + ii], w, acc[bb]);
    }
#pragma unroll
    for (int bb = 0; bb < BB; bb++)
        atomicAdd(&out[bb * N + j], acc[bb]);
}

// ---------------------------------------------------------------------------
// Flash-decoding attention, split over time, with FUSED split-combine:
// the last block to finish for a given (b,h) merges all split partials,
// writes y_attn, and emits k_step/v_step to out.
// grid = (NSPLIT, H, B), block = 256 (8 warps).
__global__ void attn_kernel(const float* __restrict__ past_k,
                            const float* __restrict__ past_v,
                            const int* __restrict__ idx,
                            float* __restrict__ out) {
    const int split = blockIdx.x, h = blockIdx.y, b = blockIdx.z;
    const int id = idx[b];
    const int start = split * CHUNK;
    if (start > id) return;                       // inactive split: no writes
    const int end = min(start + CHUNK - 1, id);   // inclusive
    const int nact = id / CHUNK + 1;              // number of active splits

    const int tid = threadIdx.x, warp = tid >> 5, lane = tid & 31;
    const int hw = lane >> 4, sub = lane & 15;

    const float* qkv_b = g_qkv + b * 3 * DD;
    float4 q = *(const float4*)(qkv_b + h * HDIM + 4 * sub);
    const float scale = 0.125f;  // 1/sqrt(64)
    q.x *= scale; q.y *= scale; q.z *= scale; q.w *= scale;

    float m = -1e30f, l = 0.f;
    float4 acc = make_float4(0.f, 0.f, 0.f, 0.f);

    int t = start + 2 * warp + hw;
    bool valid = (t <= end);
    float4 kk = make_float4(0.f, 0.f, 0.f, 0.f);
    float4 vv = make_float4(0.f, 0.f, 0.f, 0.f);
    if (valid) {
        size_t off = (((size_t)b * TT + t) * HH + h) * HDIM;
        const float* kp = (t == id) ? (qkv_b + DD + h * HDIM) : (past_k + off);
        const float* vp = (t == id) ? (qkv_b + 2 * DD + h * HDIM) : (past_v + off);
        kk = *(const float4*)(kp + 4 * sub);
        vv = *(const float4*)(vp + 4 * sub);
    }

    while (__ballot_sync(0xffffffffu, valid)) {
        int tn = t + 16;
        bool nvalid = (tn <= end);
        float4 kn = make_float4(0.f, 0.f, 0.f, 0.f);
        float4 vn = make_float4(0.f, 0.f, 0.f, 0.f);
        if (nvalid) {  // prefetch next K/V while computing current
            size_t off = (((size_t)b * TT + tn) * HH + h) * HDIM;
            const float* kp = (tn == id) ? (qkv_b + DD + h * HDIM) : (past_k + off);
            const float* vp = (tn == id) ? (qkv_b + 2 * DD + h * HDIM) : (past_v + off);
            kn = *(const float4*)(kp + 4 * sub);
            vn = *(const float4*)(vp + 4 * sub);
        }

        float s = q.x * kk.x + q.y * kk.y + q.z * kk.z + q.w * kk.w;
#pragma unroll
        for (int o = 8; o; o >>= 1) s += __shfl_xor_sync(0xffffffffu, s, o);
        if (!valid) s = NEG_INF;   // dead half-warp contributes p = 0

        float mn = fmaxf(m, s);    // m >= -1e30 always, so mn finite
        float c = __expf(m - mn);
        float p = __expf(s - mn);  // 0 for invalid lanes
        l = l * c + p;
        acc.x = acc.x * c + p * vv.x;
        acc.y = acc.y * c + p * vv.y;
        acc.z = acc.z * c + p * vv.z;
        acc.w = acc.w * c + p * vv.w;
        m = mn;

        kk = kn; vv = vn; t = tn; valid = nvalid;
    }

    // merge the two half-warps (dims match: both halves hold dims 4*sub..)
    {
        float mo = __shfl_xor_sync(0xffffffffu, m, 16);
        float lo = __shfl_xor_sync(0xffffffffu, l, 16);
        float4 ao;
        ao.x = __shfl_xor_sync(0xffffffffu, acc.x, 16);
        ao.y = __shfl_xor_sync(0xffffffffu, acc.y, 16);
        ao.z = __shfl_xor_sync(0xffffffffu, acc.z, 16);
        ao.w = __shfl_xor_sync(0xffffffffu, acc.w, 16);
        float M = fmaxf(m, mo);
        float e1 = __expf(m - M), e2 = __expf(mo - M);
        l = l * e1 + lo * e2;
        acc.x = acc.x * e1 + ao.x * e2;
        acc.y = acc.y * e1 + ao.y * e2;
        acc.z = acc.z * e1 + ao.z * e2;
        acc.w = acc.w * e1 + ao.w * e2;
        m = M;
    }

    // merge 8 warps via shared memory
    __shared__ float sm[8], sl[8];
    __shared__ float4 sa[8][16];
    if (lane == 0) { sm[warp] = m; sl[warp] = l; }
    if (hw == 0) sa[warp][sub] = acc;
    __syncthreads();

    float* part_base0 = &g_part[((size_t)b * HH + h) * NSPLIT * 66];
    if (tid < HDIM) {
        float M = -1e30f;
#pragma unroll
        for (int w = 0; w < 8; w++) M = fmaxf(M, sm[w]);
        float L = 0.f, A = 0.f;
#pragma unroll
        for (int w = 0; w < 8; w++) {
            float e = __expf(sm[w] - M);
            L += e * sl[w];
            A += e * ((const float*)&sa[w][0])[tid];
        }
        float* part = part_base0 + (size_t)split * 66;
        if (tid == 0) { part[0] = M; part[1] = L; }
        part[2 + tid] = A;
    }
    __syncthreads();

    // ---- last-block-done: the final arriving block combines all splits ----
    __shared__ int is_last;
    if (tid == 0) {
        __threadfence();                         // publish partials
        int old = atomicAdd(&g_cnt[b * HH + h], 1);
        is_last = (old == nact - 1);
        if (is_last) g_cnt[b * HH + h] = 0;      // self-reset for next replay
    }
    __syncthreads();
    if (!is_last) return;

    // stage all active partials into smem with parallel (high-MLP) loads
    __shared__ float sp[NSPLIT * 66];
    int tot = nact * 66;
    for (int i = tid; i < tot; i += 256) sp[i] = part_base0[i];
    __syncthreads();

    // 4 groups x 64 dims reduction over splits
    int g = tid >> 6;       // 0..3
    int d = tid & 63;

    float M = -1e30f;
    for (int s = g; s < nact; s += 4) M = fmaxf(M, sp[s * 66]);
    float L = 0.f, A = 0.f;
    for (int s = g; s < nact; s += 4) {
        float e = __expf(sp[s * 66] - M);
        L += e * sp[s * 66 + 1];
        A += e * sp[s * 66 + 2 + d];
    }

    __shared__ float shm[4], shl[4], sha[4][HDIM];
    if (d == 0) { shm[g] = M; shl[g] = L; }
    sha[g][d] = A;
    __syncthreads();

    int j = h * HDIM + d;
    if (g == 0) {
        float MM = fmaxf(fmaxf(shm[0], shm[1]), fmaxf(shm[2], shm[3]));
        float LL = 0.f, AA = 0.f;
#pragma unroll
        for (int gg = 0; gg < 4; gg++) {
            float e = __expf(shm[gg] - MM);
            LL += e * shl[gg];
            AA += e * sha[gg][d];
        }
        g_yattn[b * DD + j] = AA / LL;
    } else if (g == 2) {
        out[BB * DD + b * DD + j] = qkv_b[DD + j];                     // k_step
    } else if (g == 3) {
        out[2 * BB * DD + b * DD + j] = qkv_b[2 * DD + j];             // v_step
    }
}

// ---------------------------------------------------------------------------
extern "C" void kernel_launch(void* const* d_in, const int* in_sizes, int n_in,
                              void* d_out, int out_size) {
    const float* x      = (const float*)d_in[0];
    const float* past_k = (const float*)d_in[1];
    const float* past_v = (const float*)d_in[2];
    const int*   idx    = (const int*)d_in[3];
    const float* W_attn = (const float*)d_in[4];
    const float* b_attn = (const float*)d_in[5];
    const float* W_proj = (const float*)d_in[6];
    const float* b_proj = (const float*)d_in[7];
    float* out = (float*)d_out;

    float* qkv_ptr = nullptr;
    float* yattn_ptr = nullptr;
    cudaGetSymbolAddress((void**)&qkv_ptr, g_qkv);
    cudaGetSymbolAddress((void**)&yattn_ptr, g_yattn);

    // 1. qkv = bias; out y-region = b_proj
    init_qkv_kernel<<<24, 1024>>>(b_attn, b_proj, out);
    // 2. qkv += x @ W_attn   (split-K, cp.async-staged W tile)
    gemm_splitk_kernel<<<dim3(12, 32), 256>>>(x, W_attn, qkv_ptr, 3 * DD);
    // 3. flash-decode attention partials + fused combine/output-emit
    attn_kernel<<<dim3(NSPLIT, HH, BB), 256>>>(past_k, past_v, idx, out);
    // 4. y += y_attn @ W_proj
    gemm_splitk_kernel<<<dim3(4, 32), 256>>>(yattn_ptr, W_proj, out, DD);
}

// round 13
// speedup vs baseline: 3.0369x; 1.0068x over previous
#include <cuda_runtime.h>
#include <math.h>

#define BB 8
#define TT 8192
#define DD 1024
#define HH 16
#define HDIM 64
#define NSPLIT 32
#define CHUNK 256

#define NEG_INF (-__int_as_float(0x7f800000) * 1.0f)

// Scratch (static __device__ arrays — no allocation allowed)
__device__ float g_qkv[BB * 3 * DD];                 // [B, 3D]
__device__ float g_part[BB * HH * NSPLIT * 66];      // per-split: m, l, acc[64]
__device__ float g_yattn[BB * DD];                   // [B, H*HD]
__device__ int   g_cnt[BB * HH];                     // arrival counters (self-resetting)

// ---------------------------------------------------------------------------
// Init: qkv = bias (broadcast), and seed out's y region with b_proj
__global__ void init_qkv_kernel(const float* __restrict__ b_attn,
                                const float* __restrict__ b_proj,
                                float* __restrict__ out) {
    int i = blockIdx.x * blockDim.x + threadIdx.x;
    if (i < BB * 3 * DD) g_qkv[i] = b_attn[i % (3 * DD)];
    if (i < BB * DD) out[i] = b_proj[i % DD];
}

// ---------------------------------------------------------------------------
// Split-K GEMV-batch: out[b, j] += sum_i X[b, i] * W[i, j]   (Kdim = 1024)
// grid.x = N/256 column blocks, grid.y = 64 k-blocks of KB=16.
// W tile staged via 16-byte cp.async.cg (4 wide ops/thread, fire-and-forget:
// ptxas cannot serialize them). KB=16 -> 16KB smem -> several blocks/SM so
// loads of one block overlap latency of another (R10: one wave, one block/SM
// left the transfer latency fully exposed at 695 GB/s).
__global__ void __launch_bounds__(256) gemm_splitk_kernel(
        const float* __restrict__ X,
        const float* __restrict__ W,
        float* __restrict__ out, int N) {
    const int KB = 16;
    const int tid = threadIdx.x;
    const int jb = blockIdx.x * 256;
    const int j = jb + tid;
    const int i0 = blockIdx.y * KB;

    __shared__ float xs[BB * KB];      // 512 B
    __shared__ float ws[KB][256];      // 16 KB

    // async-stage the 16x256 W tile: 1024 float4s, 4 per thread
    unsigned ws_base = (unsigned)__cvta_generic_to_shared(&ws[0][0]);
#pragma unroll
    for (int r = 0; r < 4; r++) {
        int f = r * 256 + tid;            // float4 index
        int row = f >> 6, c4 = f & 63;    // 64 float4 per row
        const float* src = W + (size_t)(i0 + row) * N + jb + c4 * 4;
        asm volatile("cp.async.cg.shared.global [%0], [%1], 16;\n"
                     :: "r"(ws_base + f * 16), "l"(src));
    }
    asm volatile("cp.async.commit_group;\n" ::: "memory");

    // x tile via regular load (tiny; overlaps the async group)
    if (tid < BB * KB) {
        int bb = tid >> 4, ii = tid & 15;
        xs[tid] = X[bb * DD + i0 + ii];
    }

    asm volatile("cp.async.wait_group 0;\n" ::: "memory");
    __syncthreads();

    float acc[BB];
#pragma unroll
    for (int bb = 0; bb < BB; bb++) acc[bb] = 0.f;

#pragma unroll
    for (int ii = 0; ii < KB; ii++) {
        float w = ws[ii][tid];
#pragma unroll
        for (int bb = 0; bb < BB; bb++)
            acc[bb] = fmaf(xs[bb * KB + ii], w, acc[bb]);
    }
#pragma unroll
    for (int bb = 0; bb < BB; bb++)
        atomicAdd(&out[bb * N + j], acc[bb]);
}

// ---------------------------------------------------------------------------
// Flash-decoding attention, split over time, with FUSED split-combine:
// the last block to finish for a given (b,h) merges all split partials,
// writes y_attn, and emits k_step/v_step to out.
// grid = (NSPLIT, H, B), block = 256 (8 warps).
__global__ void attn_kernel(const float* __restrict__ past_k,
                            const float* __restrict__ past_v,
                            const int* __restrict__ idx,
                            float* __restrict__ out) {
    const int split = blockIdx.x, h = blockIdx.y, b = blockIdx.z;
    const int id = idx[b];
    const int start = split * CHUNK;
    if (start > id) return;                       // inactive split: no writes
    const int end = min(start + CHUNK - 1, id);   // inclusive
    const int nact = id / CHUNK + 1;              // number of active splits

    const int tid = threadIdx.x, warp = tid >> 5, lane = tid & 31;
    const int hw = lane >> 4, sub = lane & 15;

    const float* qkv_b = g_qkv + b * 3 * DD;
    float4 q = *(const float4*)(qkv_b + h * HDIM + 4 * sub);
    const float scale = 0.125f;  // 1/sqrt(64)
    q.x *= scale; q.y *= scale; q.z *= scale; q.w *= scale;

    float m = -1e30f, l = 0.f;
    float4 acc = make_float4(0.f, 0.f, 0.f, 0.f);

    int t = start + 2 * warp + hw;
    bool valid = (t <= end);
    float4 kk = make_float4(0.f, 0.f, 0.f, 0.f);
    float4 vv = make_float4(0.f, 0.f, 0.f, 0.f);
    if (valid) {
        size_t off = (((size_t)b * TT + t) * HH + h) * HDIM;
        const float* kp = (t == id) ? (qkv_b + DD + h * HDIM) : (past_k + off);
        const float* vp = (t == id) ? (qkv_b + 2 * DD + h * HDIM) : (past_v + off);
        kk = *(const float4*)(kp + 4 * sub);
        vv = *(const float4*)(vp + 4 * sub);
    }

    while (__ballot_sync(0xffffffffu, valid)) {
        int tn = t + 16;
        bool nvalid = (tn <= end);
        float4 kn = make_float4(0.f, 0.f, 0.f, 0.f);
        float4 vn = make_float4(0.f, 0.f, 0.f, 0.f);
        if (nvalid) {  // prefetch next K/V while computing current
            size_t off = (((size_t)b * TT + tn) * HH + h) * HDIM;
            const float* kp = (tn == id) ? (qkv_b + DD + h * HDIM) : (past_k + off);
            const float* vp = (tn == id) ? (qkv_b + 2 * DD + h * HDIM) : (past_v + off);
            kn = *(const float4*)(kp + 4 * sub);
            vn = *(const float4*)(vp + 4 * sub);
        }

        float s = q.x * kk.x + q.y * kk.y + q.z * kk.z + q.w * kk.w;
#pragma unroll
        for (int o = 8; o; o >>= 1) s += __shfl_xor_sync(0xffffffffu, s, o);
        if (!valid) s = NEG_INF;   // dead half-warp contributes p = 0

        float mn = fmaxf(m, s);    // m >= -1e30 always, so mn finite
        float c = __expf(m - mn);
        float p = __expf(s - mn);  // 0 for invalid lanes
        l = l * c + p;
        acc.x = acc.x * c + p * vv.x;
        acc.y = acc.y * c + p * vv.y;
        acc.z = acc.z * c + p * vv.z;
        acc.w = acc.w * c + p * vv.w;
        m = mn;

        kk = kn; vv = vn; t = tn; valid = nvalid;
    }

    // merge the two half-warps (dims match: both halves hold dims 4*sub..)
    {
        float mo = __shfl_xor_sync(0xffffffffu, m, 16);
        float lo = __shfl_xor_sync(0xffffffffu, l, 16);
        float4 ao;
        ao.x = __shfl_xor_sync(0xffffffffu, acc.x, 16);
        ao.y = __shfl_xor_sync(0xffffffffu, acc.y, 16);
        ao.z = __shfl_xor_sync(0xffffffffu, acc.z, 16);
        ao.w = __shfl_xor_sync(0xffffffffu, acc.w, 16);
        float M = fmaxf(m, mo);
        float e1 = __expf(m - M), e2 = __expf(mo - M);
        l = l * e1 + lo * e2;
        acc.x = acc.x * e1 + ao.x * e2;
        acc.y = acc.y * e1 + ao.y * e2;
        acc.z = acc.z * e1 + ao.z * e2;
        acc.w = acc.w * e1 + ao.w * e2;
        m = M;
    }

    // merge 8 warps via shared memory
    __shared__ float sm[8], sl[8];
    __shared__ float4 sa[8][16];
    if (lane == 0) { sm[warp] = m; sl[warp] = l; }
    if (hw == 0) sa[warp][sub] = acc;
    __syncthreads();

    float* part_base0 = &g_part[((size_t)b * HH + h) * NSPLIT * 66];
    if (tid < HDIM) {
        float M = -1e30f;
#pragma unroll
        for (int w = 0; w < 8; w++) M = fmaxf(M, sm[w]);
        float L = 0.f, A = 0.f;
#pragma unroll
        for (int w = 0; w < 8; w++) {
            float e = __expf(sm[w] - M);
            L += e * sl[w];
            A += e * ((const float*)&sa[w][0])[tid];
        }
        float* part = part_base0 + (size_t)split * 66;
        if (tid == 0) { part[0] = M; part[1] = L; }
        part[2 + tid] = A;
    }
    __syncthreads();

    // ---- last-block-done: the final arriving block combines all splits ----
    __shared__ int is_last;
    if (tid == 0) {
        __threadfence();                         // publish partials
        int old = atomicAdd(&g_cnt[b * HH + h], 1);
        is_last = (old == nact - 1);
        if (is_last) g_cnt[b * HH + h] = 0;      // self-reset for next replay
    }
    __syncthreads();
    if (!is_last) return;

    // stage all active partials into smem with parallel (high-MLP) loads
    __shared__ float sp[NSPLIT * 66];
    int tot = nact * 66;
    for (int i = tid; i < tot; i += 256) sp[i] = part_base0[i];
    __syncthreads();

    // 4 groups x 64 dims reduction over splits
    int g = tid >> 6;       // 0..3
    int d = tid & 63;

    float M = -1e30f;
    for (int s = g; s < nact; s += 4) M = fmaxf(M, sp[s * 66]);
    float L = 0.f, A = 0.f;
    for (int s = g; s < nact; s += 4) {
        float e = __expf(sp[s * 66] - M);
        L += e * sp[s * 66 + 1];
        A += e * sp[s * 66 + 2 + d];
    }

    __shared__ float shm[4], shl[4], sha[4][HDIM];
    if (d == 0) { shm[g] = M; shl[g] = L; }
    sha[g][d] = A;
    __syncthreads();

    int j = h * HDIM + d;
    if (g == 0) {
        float MM = fmaxf(fmaxf(shm[0], shm[1]), fmaxf(shm[2], shm[3]));
        float LL = 0.f, AA = 0.f;
#pragma unroll
        for (int gg = 0; gg < 4; gg++) {
            float e = __expf(shm[gg] - MM);
            LL += e * shl[gg];
            AA += e * sha[gg][d];
        }
        g_yattn[b * DD + j] = AA / LL;
    } else if (g == 2) {
        out[BB * DD + b * DD + j] = qkv_b[DD + j];                     // k_step
    } else if (g == 3) {
        out[2 * BB * DD + b * DD + j] = qkv_b[2 * DD + j];             // v_step
    }
}

// ---------------------------------------------------------------------------
extern "C" void kernel_launch(void* const* d_in, const int* in_sizes, int n_in,
                              void* d_out, int out_size) {
    const float* x      = (const float*)d_in[0];
    const float* past_k = (const float*)d_in[1];
    const float* past_v = (const float*)d_in[2];
    const int*   idx    = (const int*)d_in[3];
    const float* W_attn = (const float*)d_in[4];
    const float* b_attn = (const float*)d_in[5];
    const float* W_proj = (const float*)d_in[6];
    const float* b_proj = (const float*)d_in[7];
    float* out = (float*)d_out;

    float* qkv_ptr = nullptr;
    float* yattn_ptr = nullptr;
    cudaGetSymbolAddress((void**)&qkv_ptr, g_qkv);
    cudaGetSymbolAddress((void**)&yattn_ptr, g_yattn);

    // 1. qkv = bias; out y-region = b_proj
    init_qkv_kernel<<<24, 1024>>>(b_attn, b_proj, out);
    // 2. qkv += x @ W_attn   (split-K 64x16, float4 cp.async staging)
    gemm_splitk_kernel<<<dim3(12, 64), 256>>>(x, W_attn, qkv_ptr, 3 * DD);
    // 3. flash-decode attention partials + fused combine/output-emit
    attn_kernel<<<dim3(NSPLIT, HH, BB), 256>>>(past_k, past_v, idx, out);
    // 4. y += y_attn @ W_proj
    gemm_splitk_kernel<<<dim3(4, 64), 256>>>(yattn_ptr, W_proj, out, DD);
}